// round 10
// baseline (speedup 1.0000x reference)
#include <cuda_runtime.h>
#include <stdint.h>

// pointclouds: (32, 131072, 6) f32, task_transform: (32, 4, 4) f32
// Stable-partition each batch: valid rows (original values, original order)
// first, rest zero.

#define BATCH 32
#define NPTS 131072
#define TILE 2048
#define NTILES (NPTS / TILE)            // 64
#define THREADS 256
#define ITEMS (TILE / THREADS)          // 8
#define WORDS (TILE / 32)               // 64 flag words per tile
#define VEC4 (TILE * 6 / 4 / THREADS)   // 12 float4 per thread
#define SROW_BYTES (TILE * 6 * 4)       // 49152 B dynamic smem

#define FLAG_AGG 0x40000000u
#define FLAG_INC 0x80000000u
#define VAL_MASK 0x00FFFFFFu

__device__ unsigned int g_state[BATCH * NTILES];

// ---------------------------------------------------------------------------
// K0: reset lookback tile states (runs inside the graph on every replay).
// ---------------------------------------------------------------------------
__global__ void k_init()
{
    for (int i = blockIdx.x * blockDim.x + threadIdx.x;
         i < BATCH * NTILES; i += gridDim.x * blockDim.x)
        g_state[i] = 0u;
}

// ---------------------------------------------------------------------------
// K1: single-pass stable compaction + fused tail zeroing, smem-staged.
// grid (NTILES, BATCH), 256 threads, 48KB dynamic smem.
// ---------------------------------------------------------------------------
__global__ void __launch_bounds__(THREADS) k_compact(
    const float* __restrict__ pc, const float* __restrict__ tt,
    float* __restrict__ out)
{
    extern __shared__ float srow[];      // staged tile, 48KB (dynamic)

    const int b    = blockIdx.y;
    const int tile = blockIdx.x;
    const int tid  = threadIdx.x;
    const int lane = tid & 31, warp = tid >> 5;

    __shared__ float T[12];
    __shared__ unsigned sw[WORDS];
    __shared__ int sscan[WORDS];         // inclusive popc scan
    __shared__ int sbase;

    if (tid < 12) T[tid] = tt[b * 16 + tid];

    const float* src = pc + (size_t)b * NPTS * 6;
    const int p0 = tile * TILE;

    // --- Phase 1: coalesced float4 stage gmem -> smem ---
    {
        const float4* s4 = (const float4*)(src + (size_t)p0 * 6);
        float4* d4 = (float4*)srow;
#pragma unroll
        for (int i = 0; i < VEC4; i++)
            d4[i * THREADS + tid] = s4[i * THREADS + tid];
    }
    __syncthreads();

    const float r00 = T[0],  r01 = T[1],  r02 = T[2],  tx = T[3];
    const float r10 = T[4],  r11 = T[5],  r12 = T[6],  ty = T[7];
    const float r20 = T[8],  r21 = T[9],  r22 = T[10], tz = T[11];

    // --- Phase 2: flags from smem; keep each item's ballot word in regs ---
    unsigned mreg[ITEMS];
#pragma unroll
    for (int i = 0; i < ITEMS; i++) {
        const int l = i * THREADS + tid;         // local row
        const float* r = &srow[l * 6];
        const float x = r[0], y = r[1], z = r[2];
        const float nsum = r[3] + r[4] + r[5];

        const float px = x * r00 + y * r10 + z * r20 + tx;
        const float py = x * r01 + y * r11 + z * r21 + ty;
        const float pz = x * r02 + y * r12 + z * r22 + tz;

        const bool v = (px * px + py * py < 1.0f) && (pz < 1.0f) && (nsum != 0.0f);
        const unsigned m = __ballot_sync(0xffffffffu, v);
        mreg[i] = m;
        if (lane == 0) sw[i * (THREADS / 32) + warp] = m;
    }
    __syncthreads();

    // --- Phase 3a: inclusive scan of the 64 word popcounts (2 warps) ---
    if (tid < WORDS) {
        int v = __popc(sw[tid]);
#pragma unroll
        for (int off = 1; off < 32; off <<= 1) {
            const int n = __shfl_up_sync(0xffffffffu, v, off);
            if ((tid & 31) >= off) v += n;
        }
        sscan[tid] = v;
    }
    __syncthreads();
    if (tid >= 32 && tid < WORDS) sscan[tid] += sscan[31];
    __syncthreads();

    const int cnt = sscan[WORDS - 1];

    // --- Phase 3b: warp-parallel decoupled lookback (warp 0) ---
    if (tid < 32) {
        unsigned* stArr = &g_state[b * NTILES];
        if (tile == 0) {
            if (lane == 0) {
                atomicExch(&stArr[0], FLAG_INC | (unsigned)cnt);
                sbase = 0;
            }
        } else {
            if (lane == 0) atomicExch(&stArr[tile], FLAG_AGG | (unsigned)cnt);
            int run = 0;
            int p = tile - 1 - lane;       // lane 0 = nearest predecessor
            for (;;) {
                unsigned v;
                if (p >= 0) {
                    do { v = *(volatile unsigned*)&stArr[p]; }
                    while ((v & (FLAG_AGG | FLAG_INC)) == 0u);
                } else {
                    v = FLAG_INC;          // virtual tile -1 with prefix 0
                }
                const unsigned incs =
                    __ballot_sync(0xffffffffu, (v & FLAG_INC) != 0u);
                int contrib;
                if (incs) {
                    const int L = __ffs(incs) - 1;   // nearest INC
                    contrib = (lane <= L) ? (int)(v & VAL_MASK) : 0;
                } else {
                    contrib = (int)(v & VAL_MASK);
                }
#pragma unroll
                for (int o = 16; o; o >>= 1)
                    contrib += __shfl_down_sync(0xffffffffu, contrib, o);
                run += __shfl_sync(0xffffffffu, contrib, 0);
                if (incs) break;
                p -= 32;
            }
            if (lane == 0) {
                sbase = run;
                atomicExch(&stArr[tile], FLAG_INC | (unsigned)(run + cnt));
            }
        }
    }
    __syncthreads();

    const int base = sbase;
    float* dst = out + (size_t)b * NPTS * 6;

    // --- Phase 4: direct stable scatter from smem ---
    // Thread's item i is valid iff bit `lane` of mreg[i]. Its rank is the
    // word-exclusive prefix + popc of lower lanes; set lanes of a warp write
    // consecutive ranks -> contiguous 24B-packed stores.
#pragma unroll
    for (int i = 0; i < ITEMS; i++) {
        const unsigned m = mreg[i];
        if ((m >> lane) & 1u) {
            const int w = i * (THREADS / 32) + warp;
            const int rank = (w ? sscan[w - 1] : 0)
                           + __popc(m & ((1u << lane) - 1u));
            const int l = i * THREADS + tid;
            const float2* r2 = (const float2*)&srow[l * 6];
            float2* o = (float2*)(dst + (size_t)(base + rank) * 6);
            __stcs(&o[0], r2[0]);
            __stcs(&o[1], r2[1]);
            __stcs(&o[2], r2[2]);
        }
    }

    // --- Phase 5: fused tail zeroing ---
    // Exclusive invalid-prefix of this tile = p0 - base; zero output rows
    // [NPTS - inv_prefix - inv, NPTS - inv_prefix); disjoint across tiles,
    // union = [total, NPTS).
    const int inv = TILE - cnt;
    if (inv > 0) {
        const int inv_prefix = p0 - base;
        const int row0 = NPTS - inv_prefix - inv;
        float2* z2 = (float2*)(dst + (size_t)row0 * 6);
        const int n2 = inv * 3;                  // float2 count
        const float2 z = make_float2(0.0f, 0.0f);
        for (int i = tid; i < n2; i += THREADS) __stcs(&z2[i], z);
    }
}

// ---------------------------------------------------------------------------
extern "C" void kernel_launch(void* const* d_in, const int* in_sizes, int n_in,
                              void* d_out, int out_size)
{
    const float* pc = (const float*)d_in[0];   // (32, 131072, 6)
    const float* tt = (const float*)d_in[1];   // (32, 4, 4)
    float* out = (float*)d_out;

    // Opt-in to >48KB dynamic smem (attribute set, not an allocation;
    // executes immediately even under graph capture).
    static bool attr_done = false;
    if (!attr_done) {
        cudaFuncSetAttribute(k_compact,
                             cudaFuncAttributeMaxDynamicSharedMemorySize,
                             SROW_BYTES);
        attr_done = true;
    }

    k_init<<<8, THREADS>>>();
    dim3 gc(NTILES, BATCH);
    k_compact<<<gc, THREADS, SROW_BYTES>>>(pc, tt, out);
}

// round 17
// speedup vs baseline: 1.0528x; 1.0528x over previous
#include <cuda_runtime.h>
#include <stdint.h>

// pointclouds: (32, 131072, 6) f32, task_transform: (32, 4, 4) f32
// Stable-partition each batch: valid rows (original values, original order)
// first, rest zero.

#define BATCH 32
#define NPTS 131072
#define TILE 1024
#define NTILES (NPTS / TILE)            // 128
#define THREADS 256
#define ITEMS (TILE / THREADS)          // 4
#define WORDS (TILE / 32)               // 32 flag words per tile
#define VEC4 (TILE * 6 / 4 / THREADS)   // 6 float4 per thread
#define SROW_BYTES (TILE * 6 * 4)       // 24576 B dynamic smem

#define FLAG_AGG 0x40000000u
#define FLAG_INC 0x80000000u
#define VAL_MASK 0x00FFFFFFu

__device__ unsigned int g_state[BATCH * NTILES];

// ---------------------------------------------------------------------------
// K0: reset lookback tile states (runs inside the graph on every replay).
// ---------------------------------------------------------------------------
__global__ void k_init()
{
    for (int i = blockIdx.x * blockDim.x + threadIdx.x;
         i < BATCH * NTILES; i += gridDim.x * blockDim.x)
        g_state[i] = 0u;
}

// ---------------------------------------------------------------------------
// K1: single-pass stable compaction + fused tail zeroing, smem-staged.
// grid (NTILES, BATCH), 256 threads, 24KB dynamic smem -> 8 blocks/SM.
// ---------------------------------------------------------------------------
__global__ void __launch_bounds__(THREADS) k_compact(
    const float* __restrict__ pc, const float* __restrict__ tt,
    float* __restrict__ out)
{
    extern __shared__ float srow[];      // staged tile, 24KB (dynamic)

    const int b    = blockIdx.y;
    const int tile = blockIdx.x;
    const int tid  = threadIdx.x;
    const int lane = tid & 31, warp = tid >> 5;

    __shared__ float T[12];
    __shared__ unsigned sw[WORDS];
    __shared__ int sscan[WORDS];         // inclusive popc scan
    __shared__ int sbase;

    if (tid < 12) T[tid] = tt[b * 16 + tid];

    const float* src = pc + (size_t)b * NPTS * 6;
    const int p0 = tile * TILE;

    // --- Phase 1: coalesced float4 stage gmem -> smem ---
    {
        const float4* s4 = (const float4*)(src + (size_t)p0 * 6);
        float4* d4 = (float4*)srow;
#pragma unroll
        for (int i = 0; i < VEC4; i++)
            d4[i * THREADS + tid] = s4[i * THREADS + tid];
    }
    __syncthreads();

    const float r00 = T[0],  r01 = T[1],  r02 = T[2],  tx = T[3];
    const float r10 = T[4],  r11 = T[5],  r12 = T[6],  ty = T[7];
    const float r20 = T[8],  r21 = T[9],  r22 = T[10], tz = T[11];

    // --- Phase 2: flags from smem; keep each item's ballot word in regs ---
    unsigned mreg[ITEMS];
#pragma unroll
    for (int i = 0; i < ITEMS; i++) {
        const int l = i * THREADS + tid;         // local row
        const float* r = &srow[l * 6];
        const float x = r[0], y = r[1], z = r[2];
        const float nsum = r[3] + r[4] + r[5];

        const float px = x * r00 + y * r10 + z * r20 + tx;
        const float py = x * r01 + y * r11 + z * r21 + ty;
        const float pz = x * r02 + y * r12 + z * r22 + tz;

        const bool v = (px * px + py * py < 1.0f) && (pz < 1.0f) && (nsum != 0.0f);
        const unsigned m = __ballot_sync(0xffffffffu, v);
        mreg[i] = m;
        if (lane == 0) sw[i * (THREADS / 32) + warp] = m;
    }
    __syncthreads();

    // --- Phase 3a: inclusive scan of the 32 word popcounts (1 warp) ---
    if (tid < WORDS) {
        int v = __popc(sw[tid]);
#pragma unroll
        for (int off = 1; off < 32; off <<= 1) {
            const int n = __shfl_up_sync(0xffffffffu, v, off);
            if (lane >= off) v += n;
        }
        sscan[tid] = v;
    }
    __syncthreads();

    const int cnt = sscan[WORDS - 1];

    // --- Phase 3b: warp-parallel decoupled lookback (warp 0) ---
    if (tid < 32) {
        unsigned* stArr = &g_state[b * NTILES];
        if (tile == 0) {
            if (lane == 0) {
                atomicExch(&stArr[0], FLAG_INC | (unsigned)cnt);
                sbase = 0;
            }
        } else {
            if (lane == 0) atomicExch(&stArr[tile], FLAG_AGG | (unsigned)cnt);
            int run = 0;
            int p = tile - 1 - lane;       // lane 0 = nearest predecessor
            for (;;) {
                unsigned v;
                if (p >= 0) {
                    do { v = *(volatile unsigned*)&stArr[p]; }
                    while ((v & (FLAG_AGG | FLAG_INC)) == 0u);
                } else {
                    v = FLAG_INC;          // virtual tile -1 with prefix 0
                }
                const unsigned incs =
                    __ballot_sync(0xffffffffu, (v & FLAG_INC) != 0u);
                int contrib;
                if (incs) {
                    const int L = __ffs(incs) - 1;   // nearest INC
                    contrib = (lane <= L) ? (int)(v & VAL_MASK) : 0;
                } else {
                    contrib = (int)(v & VAL_MASK);
                }
#pragma unroll
                for (int o = 16; o; o >>= 1)
                    contrib += __shfl_down_sync(0xffffffffu, contrib, o);
                run += __shfl_sync(0xffffffffu, contrib, 0);
                if (incs) break;
                p -= 32;
            }
            if (lane == 0) {
                sbase = run;
                atomicExch(&stArr[tile], FLAG_INC | (unsigned)(run + cnt));
            }
        }
    }
    __syncthreads();

    const int base = sbase;
    float* dst = out + (size_t)b * NPTS * 6;

    // --- Phase 4: direct stable scatter from smem ---
    // Thread's item i is valid iff bit `lane` of mreg[i]. Its rank is the
    // word-exclusive prefix + popc of lower lanes; set lanes of a warp write
    // consecutive ranks -> contiguous 24B-packed stores.
#pragma unroll
    for (int i = 0; i < ITEMS; i++) {
        const unsigned m = mreg[i];
        if ((m >> lane) & 1u) {
            const int w = i * (THREADS / 32) + warp;
            const int rank = (w ? sscan[w - 1] : 0)
                           + __popc(m & ((1u << lane) - 1u));
            const int l = i * THREADS + tid;
            const float2* r2 = (const float2*)&srow[l * 6];
            float2* o = (float2*)(dst + (size_t)(base + rank) * 6);
            __stcs(&o[0], r2[0]);
            __stcs(&o[1], r2[1]);
            __stcs(&o[2], r2[2]);
        }
    }

    // --- Phase 5: fused tail zeroing ---
    // Exclusive invalid-prefix of this tile = p0 - base; zero output rows
    // [NPTS - inv_prefix - inv, NPTS - inv_prefix); disjoint across tiles,
    // union = [total, NPTS).
    const int inv = TILE - cnt;
    if (inv > 0) {
        const int inv_prefix = p0 - base;
        const int row0 = NPTS - inv_prefix - inv;
        float2* z2 = (float2*)(dst + (size_t)row0 * 6);
        const int n2 = inv * 3;                  // float2 count
        const float2 z = make_float2(0.0f, 0.0f);
        for (int i = tid; i < n2; i += THREADS) __stcs(&z2[i], z);
    }
}

// ---------------------------------------------------------------------------
extern "C" void kernel_launch(void* const* d_in, const int* in_sizes, int n_in,
                              void* d_out, int out_size)
{
    const float* pc = (const float*)d_in[0];   // (32, 131072, 6)
    const float* tt = (const float*)d_in[1];   // (32, 4, 4)
    float* out = (float*)d_out;

    k_init<<<32, THREADS>>>();
    dim3 gc(NTILES, BATCH);
    k_compact<<<gc, THREADS, SROW_BYTES>>>(pc, tt, out);
}